// round 1
// baseline (speedup 1.0000x reference)
#include <cuda_runtime.h>
#include <cuda_bf16.h>
#include <math.h>

#define BATCH 2
#define SEQ   2048
#define DMODEL 1024
#define NHEADS 16
#define DHEAD 64
#define MROWS (BATCH*SEQ)   // 4096

// ---------------- scratch (alloc-free rule: __device__ globals) ----------------
__device__ float g_Q[MROWS * DMODEL];
__device__ float g_K[MROWS * DMODEL];
__device__ float g_V[MROWS * DMODEL];
__device__ float g_AO[MROWS * DMODEL];

// ---------------- generic tiled GEMM:  C = A * W^T + bias ----------------
// A: [M, K] row-major, W: [N, K] row-major, C: [M, N]
#define GBM 64
#define GBN 64
#define GBK 16

__global__ __launch_bounds__(256) void gemm_bias_kernel(
    const float* __restrict__ A, const float* __restrict__ W,
    const float* __restrict__ bias, float* __restrict__ C,
    int Mdim, int Ndim, int Kdim)
{
    __shared__ float As[GBK][GBM];
    __shared__ float Ws[GBK][GBN];

    const int tx = threadIdx.x;          // 0..15
    const int ty = threadIdx.y;          // 0..15
    const int tid = ty * 16 + tx;        // 0..255
    const int bm = blockIdx.y * GBM;
    const int bn = blockIdx.x * GBN;

    const int lrow = tid >> 2;           // 0..63
    const int lcg  = (tid & 3) * 4;      // 0,4,8,12

    float acc[4][4] = {};

    for (int k0 = 0; k0 < Kdim; k0 += GBK) {
        // load A tile (64 rows x 16 cols), transposed into k-major smem
        float4 av = *(const float4*)&A[(size_t)(bm + lrow) * Kdim + k0 + lcg];
        As[lcg + 0][lrow] = av.x;
        As[lcg + 1][lrow] = av.y;
        As[lcg + 2][lrow] = av.z;
        As[lcg + 3][lrow] = av.w;
        // load W tile
        float4 wv = *(const float4*)&W[(size_t)(bn + lrow) * Kdim + k0 + lcg];
        Ws[lcg + 0][lrow] = wv.x;
        Ws[lcg + 1][lrow] = wv.y;
        Ws[lcg + 2][lrow] = wv.z;
        Ws[lcg + 3][lrow] = wv.w;
        __syncthreads();

        #pragma unroll
        for (int kk = 0; kk < GBK; kk++) {
            float4 a4 = *(const float4*)&As[kk][ty * 4];
            float4 w4 = *(const float4*)&Ws[kk][tx * 4];
            acc[0][0] += a4.x * w4.x; acc[0][1] += a4.x * w4.y;
            acc[0][2] += a4.x * w4.z; acc[0][3] += a4.x * w4.w;
            acc[1][0] += a4.y * w4.x; acc[1][1] += a4.y * w4.y;
            acc[1][2] += a4.y * w4.z; acc[1][3] += a4.y * w4.w;
            acc[2][0] += a4.z * w4.x; acc[2][1] += a4.z * w4.y;
            acc[2][2] += a4.z * w4.z; acc[2][3] += a4.z * w4.w;
            acc[3][0] += a4.w * w4.x; acc[3][1] += a4.w * w4.y;
            acc[3][2] += a4.w * w4.z; acc[3][3] += a4.w * w4.w;
        }
        __syncthreads();
    }

    #pragma unroll
    for (int i = 0; i < 4; i++) {
        #pragma unroll
        for (int j = 0; j < 4; j++) {
            int n = bn + tx * 4 + j;
            C[(size_t)(bm + ty * 4 + i) * Ndim + n] = acc[i][j] + bias[n];
        }
    }
}

// ---------------- flash attention (fp32, online softmax) ----------------
// Q,K,V scratch layout: [B, S, D] with head h occupying cols h*64..h*64+63
#define TQ 64
#define TK 64
#define PADF 65   // smem row pitch in floats (odd-ish: worst 2-way conflicts)

__global__ __launch_bounds__(256) void flash_attn_kernel(
    const float* __restrict__ Qg, const float* __restrict__ Kg,
    const float* __restrict__ Vg, const int* __restrict__ maskg,
    float* __restrict__ Og)
{
    extern __shared__ float sm[];
    float* Qs    = sm;                    // [64][PADF]
    float* Ks    = Qs + 64 * PADF;
    float* Vs    = Ks + 64 * PADF;
    float* Ps    = Vs + 64 * PADF;
    float* row_m = Ps + 64 * PADF;        // [64]
    float* row_l = row_m + 64;            // [64]
    float* row_s = row_l + 64;            // [64]

    const int bh = blockIdx.x;            // 0..31
    const int b  = bh >> 4;
    const int h  = bh & 15;
    const int q0 = blockIdx.y * TQ;
    const int tx = threadIdx.x, ty = threadIdx.y;
    const int tid = ty * 16 + tx;

    const float slope = exp2f(-0.5f * (float)(h + 1));
    const float inv_scale = 1.0f / 32.0f;   // 1/sqrt(1024)

    // load Q tile: 64 rows x 64 cols
    const float* Qbase = Qg + ((size_t)b * SEQ + q0) * DMODEL + h * DHEAD;
    #pragma unroll
    for (int f = tid; f < 64 * 16; f += 256) {        // float4 index
        int r = f >> 4, c4 = (f & 15) * 4;
        float4 v = *(const float4*)&Qbase[(size_t)r * DMODEL + c4];
        float* dst = &Qs[r * PADF + c4];
        dst[0] = v.x; dst[1] = v.y; dst[2] = v.z; dst[3] = v.w;
    }
    if (tid < 64) { row_m[tid] = -3.0e38f; row_l[tid] = 0.0f; }

    float o[4][4] = {};

    for (int kt = 0; kt < SEQ; kt += TK) {
        __syncthreads();   // protect Qs(first iter)/Ks/Vs/Ps reuse

        const float* Kbase = Kg + ((size_t)b * SEQ + kt) * DMODEL + h * DHEAD;
        const float* Vbase = Vg + ((size_t)b * SEQ + kt) * DMODEL + h * DHEAD;
        #pragma unroll
        for (int f = tid; f < 64 * 16; f += 256) {
            int r = f >> 4, c4 = (f & 15) * 4;
            float4 kv = *(const float4*)&Kbase[(size_t)r * DMODEL + c4];
            float* kd = &Ks[r * PADF + c4];
            kd[0] = kv.x; kd[1] = kv.y; kd[2] = kv.z; kd[3] = kv.w;
            float4 vv = *(const float4*)&Vbase[(size_t)r * DMODEL + c4];
            float* vd = &Vs[r * PADF + c4];
            vd[0] = vv.x; vd[1] = vv.y; vd[2] = vv.z; vd[3] = vv.w;
        }
        __syncthreads();

        // S = Q K^T : each thread 4q x 4k
        float s[4][4] = {};
        #pragma unroll
        for (int d = 0; d < 64; d++) {
            float qv[4], kv[4];
            #pragma unroll
            for (int i = 0; i < 4; i++) qv[i] = Qs[(ty * 4 + i) * PADF + d];
            #pragma unroll
            for (int j = 0; j < 4; j++) kv[j] = Ks[(tx * 4 + j) * PADF + d];
            #pragma unroll
            for (int i = 0; i < 4; i++)
                #pragma unroll
                for (int j = 0; j < 4; j++)
                    s[i][j] += qv[i] * kv[j];
        }

        // bias + scale + mask, write scores to Ps
        #pragma unroll
        for (int i = 0; i < 4; i++) {
            int qg = q0 + ty * 4 + i;
            const int* mrow = maskg + ((size_t)b * SEQ + qg) * SEQ + kt;
            #pragma unroll
            for (int j = 0; j < 4; j++) {
                int kc = tx * 4 + j;
                int kg = kt + kc;
                float val = (s[i][j] - slope * fabsf((float)(qg - kg))) * inv_scale;
                if (mrow[kc] == 0) val = -1.0e9f;
                Ps[(ty * 4 + i) * PADF + kc] = val;
            }
        }
        __syncthreads();

        // online softmax: 4 threads per row
        {
            int r = tid >> 2, part = tid & 3;
            float* prow = &Ps[r * PADF + part * 16];
            float mloc = -3.0e38f;
            #pragma unroll
            for (int c = 0; c < 16; c++) mloc = fmaxf(mloc, prow[c]);
            mloc = fmaxf(mloc, __shfl_xor_sync(0xffffffffu, mloc, 1));
            mloc = fmaxf(mloc, __shfl_xor_sync(0xffffffffu, mloc, 2));
            float mold = row_m[r];
            float mnew = fmaxf(mold, mloc);
            float sum = 0.0f;
            #pragma unroll
            for (int c = 0; c < 16; c++) {
                float p = expf(prow[c] - mnew);
                prow[c] = p;
                sum += p;
            }
            sum += __shfl_xor_sync(0xffffffffu, sum, 1);
            sum += __shfl_xor_sync(0xffffffffu, sum, 2);
            if (part == 0) {
                float resc = expf(mold - mnew);
                row_m[r] = mnew;
                row_l[r] = row_l[r] * resc + sum;
                row_s[r] = resc;
            }
        }
        __syncthreads();

        // O = O*rescale + P V
        float resc[4];
        #pragma unroll
        for (int i = 0; i < 4; i++) resc[i] = row_s[ty * 4 + i];
        #pragma unroll
        for (int i = 0; i < 4; i++)
            #pragma unroll
            for (int j = 0; j < 4; j++) o[i][j] *= resc[i];

        #pragma unroll
        for (int k = 0; k < 64; k++) {
            float pv[4], vv[4];
            #pragma unroll
            for (int i = 0; i < 4; i++) pv[i] = Ps[(ty * 4 + i) * PADF + k];
            #pragma unroll
            for (int j = 0; j < 4; j++) vv[j] = Vs[k * PADF + tx * 4 + j];
            #pragma unroll
            for (int i = 0; i < 4; i++)
                #pragma unroll
                for (int j = 0; j < 4; j++)
                    o[i][j] += pv[i] * vv[j];
        }
    }

    // normalize + store, output layout [B, S, D] (head-major cols)
    #pragma unroll
    for (int i = 0; i < 4; i++) {
        int qg = q0 + ty * 4 + i;
        float invl = 1.0f / row_l[ty * 4 + i];
        #pragma unroll
        for (int j = 0; j < 4; j++)
            Og[((size_t)b * SEQ + qg) * DMODEL + h * DHEAD + tx * 4 + j] = o[i][j] * invl;
    }
}

// ---------------- launcher ----------------
extern "C" void kernel_launch(void* const* d_in, const int* in_sizes, int n_in,
                              void* d_out, int out_size)
{
    const float* embed = (const float*)d_in[0];
    const float* keyi  = (const float*)d_in[1];
    const int*   mask  = (const int*)  d_in[2];
    const float* Wq    = (const float*)d_in[3];
    const float* bq    = (const float*)d_in[4];
    const float* Wk    = (const float*)d_in[5];
    const float* bk    = (const float*)d_in[6];
    const float* Wv    = (const float*)d_in[7];
    const float* bv    = (const float*)d_in[8];
    const float* Wo    = (const float*)d_in[9];
    const float* bo    = (const float*)d_in[10];
    float* out = (float*)d_out;

    float *Qp, *Kp, *Vp, *Ap;
    cudaGetSymbolAddress((void**)&Qp, g_Q);
    cudaGetSymbolAddress((void**)&Kp, g_K);
    cudaGetSymbolAddress((void**)&Vp, g_V);
    cudaGetSymbolAddress((void**)&Ap, g_AO);

    const int smem_flash = (4 * 64 * PADF + 3 * 64) * (int)sizeof(float);
    cudaFuncSetAttribute(flash_attn_kernel,
                         cudaFuncAttributeMaxDynamicSharedMemorySize, smem_flash);

    dim3 tb(16, 16);
    dim3 grid_proj(DMODEL / GBN, MROWS / GBM);   // (16, 64)

    gemm_bias_kernel<<<grid_proj, tb>>>(embed, Wq, bq, Qp, MROWS, DMODEL, DMODEL);
    gemm_bias_kernel<<<grid_proj, tb>>>(keyi,  Wk, bk, Kp, MROWS, DMODEL, DMODEL);
    gemm_bias_kernel<<<grid_proj, tb>>>(keyi,  Wv, bv, Vp, MROWS, DMODEL, DMODEL);

    dim3 grid_fa(BATCH * NHEADS, SEQ / TQ);      // (32, 32)
    flash_attn_kernel<<<grid_fa, tb, smem_flash>>>(Qp, Kp, Vp, mask, Ap);

    gemm_bias_kernel<<<grid_proj, tb>>>(Ap, Wo, bo, out, MROWS, DMODEL, DMODEL);
}

// round 2
// speedup vs baseline: 2.3665x; 2.3665x over previous
#include <cuda_runtime.h>
#include <cuda_bf16.h>
#include <math.h>

#define BATCH 2
#define SEQ   2048
#define DMODEL 1024
#define NHEADS 16
#define DHEAD 64
#define MROWS (BATCH*SEQ)   // 4096

// ---------------- scratch (alloc-free rule: __device__ globals) ----------------
__device__ float g_Q[MROWS * DMODEL];
__device__ float g_K[MROWS * DMODEL];
__device__ float g_V[MROWS * DMODEL];
__device__ float g_AO[MROWS * DMODEL];
__device__ unsigned g_MP[(size_t)BATCH * SEQ * (SEQ / 32)];   // packed mask bits

// ---------------- tf32 helpers ----------------
__device__ __forceinline__ unsigned f2tf(float x) {
    unsigned u; asm("cvt.rna.tf32.f32 %0, %1;" : "=r"(u) : "f"(x)); return u;
}
__device__ __forceinline__ float f2tff(float x) { return __uint_as_float(f2tf(x)); }

__device__ __forceinline__ void mma8(float d[4], const unsigned a[4], const unsigned b[2]) {
    asm volatile(
        "mma.sync.aligned.m16n8k8.row.col.f32.tf32.tf32.f32 "
        "{%0,%1,%2,%3},{%4,%5,%6,%7},{%8,%9},{%0,%1,%2,%3};"
        : "+f"(d[0]), "+f"(d[1]), "+f"(d[2]), "+f"(d[3])
        : "r"(a[0]), "r"(a[1]), "r"(a[2]), "r"(a[3]), "r"(b[0]), "r"(b[1]));
}

// ---------------- mask bit-packing ----------------
__global__ void pack_mask_kernel(const int* __restrict__ m, unsigned* __restrict__ p) {
    size_t i = (size_t)blockIdx.x * blockDim.x + threadIdx.x;
    unsigned bal = __ballot_sync(0xffffffffu, m[i] != 0);
    if ((threadIdx.x & 31) == 0) p[i >> 5] = bal;
}

// ---------------- tf32 GEMM:  C = A * W^T + bias ----------------
// A: [M,1024], W: [1024,1024] (row-major, K contiguous), C: [M,1024]
// Block tile 128x128, BK=32, 8 warps, warp tile 64x32 (m16n8k8).
// SPLIT=true: 3-term hi/lo split -> near-fp32 accuracy (3x mma count).
#define GPA 36   // smem pitch (floats): (g*36 + t) % 32 = g*4 + t -> conflict-free frags

template<bool SPLIT>
__global__ __launch_bounds__(256) void gemm_tf32(
    const float* __restrict__ A, const float* __restrict__ W,
    const float* __restrict__ bias, float* __restrict__ C)
{
    const int Kd = DMODEL, Nd = DMODEL;
    extern __shared__ float smg[];
    float* Ah = smg;                  // [128][36]
    float* Wh = Ah + 128 * GPA;
    float* Al = Wh + 128 * GPA;       // only used when SPLIT
    float* Wl = Al + 128 * GPA;

    const int tid = threadIdx.x, wid = tid >> 5, lane = tid & 31;
    const int g = lane >> 2, t = lane & 3;
    const int wm = (wid & 1) * 64, wn = (wid >> 1) * 32;
    const int bm = blockIdx.y * 128, bn = blockIdx.x * 128;

    float acc[4][4][4];
    #pragma unroll
    for (int mt = 0; mt < 4; mt++)
        #pragma unroll
        for (int nt = 0; nt < 4; nt++)
            #pragma unroll
            for (int r = 0; r < 4; r++) acc[mt][nt][r] = 0.0f;

    for (int k0 = 0; k0 < Kd; k0 += 32) {
        #pragma unroll
        for (int i = 0; i < 4; i++) {
            int f = tid + i * 256;            // 1024 float4 slots: 128 rows x 8
            int r = f >> 3, c4 = (f & 7) * 4;
            float4 av = *(const float4*)&A[(size_t)(bm + r) * Kd + k0 + c4];
            float4 wv = *(const float4*)&W[(size_t)(bn + r) * Kd + k0 + c4];
            float4 ah = { f2tff(av.x), f2tff(av.y), f2tff(av.z), f2tff(av.w) };
            float4 wh = { f2tff(wv.x), f2tff(wv.y), f2tff(wv.z), f2tff(wv.w) };
            *(float4*)&Ah[r * GPA + c4] = ah;
            *(float4*)&Wh[r * GPA + c4] = wh;
            if (SPLIT) {
                float4 al = { f2tff(av.x - ah.x), f2tff(av.y - ah.y),
                              f2tff(av.z - ah.z), f2tff(av.w - ah.w) };
                float4 wl = { f2tff(wv.x - wh.x), f2tff(wv.y - wh.y),
                              f2tff(wv.z - wh.z), f2tff(wv.w - wh.w) };
                *(float4*)&Al[r * GPA + c4] = al;
                *(float4*)&Wl[r * GPA + c4] = wl;
            }
        }
        __syncthreads();

        #pragma unroll
        for (int kk = 0; kk < 4; kk++) {
            unsigned a[4][4], b[4][2];
            #pragma unroll
            for (int mt = 0; mt < 4; mt++) {
                int ro = (wm + mt * 16 + g) * GPA + kk * 8 + t;
                a[mt][0] = __float_as_uint(Ah[ro]);
                a[mt][1] = __float_as_uint(Ah[ro + 8 * GPA]);
                a[mt][2] = __float_as_uint(Ah[ro + 4]);
                a[mt][3] = __float_as_uint(Ah[ro + 8 * GPA + 4]);
            }
            #pragma unroll
            for (int nt = 0; nt < 4; nt++) {
                int ro = (wn + nt * 8 + g) * GPA + kk * 8 + t;
                b[nt][0] = __float_as_uint(Wh[ro]);
                b[nt][1] = __float_as_uint(Wh[ro + 4]);
            }
            #pragma unroll
            for (int mt = 0; mt < 4; mt++)
                #pragma unroll
                for (int nt = 0; nt < 4; nt++)
                    mma8(acc[mt][nt], a[mt], b[nt]);

            if (SPLIT) {
                unsigned al[4][4], bl[4][2];
                #pragma unroll
                for (int mt = 0; mt < 4; mt++) {
                    int ro = (wm + mt * 16 + g) * GPA + kk * 8 + t;
                    al[mt][0] = __float_as_uint(Al[ro]);
                    al[mt][1] = __float_as_uint(Al[ro + 8 * GPA]);
                    al[mt][2] = __float_as_uint(Al[ro + 4]);
                    al[mt][3] = __float_as_uint(Al[ro + 8 * GPA + 4]);
                }
                #pragma unroll
                for (int nt = 0; nt < 4; nt++) {
                    int ro = (wn + nt * 8 + g) * GPA + kk * 8 + t;
                    bl[nt][0] = __float_as_uint(Wl[ro]);
                    bl[nt][1] = __float_as_uint(Wl[ro + 4]);
                }
                #pragma unroll
                for (int mt = 0; mt < 4; mt++)
                    #pragma unroll
                    for (int nt = 0; nt < 4; nt++) {
                        mma8(acc[mt][nt], al[mt], b[nt]);   // Al*Wh
                        mma8(acc[mt][nt], a[mt], bl[nt]);   // Ah*Wl
                    }
            }
        }
        __syncthreads();
    }

    #pragma unroll
    for (int mt = 0; mt < 4; mt++)
        #pragma unroll
        for (int nt = 0; nt < 4; nt++) {
            int row = bm + wm + mt * 16 + g;
            int col = bn + wn + nt * 8 + 2 * t;
            float b0 = bias[col], b1 = bias[col + 1];
            float2 v0 = { acc[mt][nt][0] + b0, acc[mt][nt][1] + b1 };
            float2 v1 = { acc[mt][nt][2] + b0, acc[mt][nt][3] + b1 };
            *(float2*)&C[(size_t)row * Nd + col] = v0;
            *(float2*)&C[(size_t)(row + 8) * Nd + col] = v1;
        }
}

// ---------------- tf32 flash attention ----------------
// Per block: one (b,h), 64 q-rows. TK=64 per iteration.
// smem pitches chosen per-operand for conflict-free mma fragment LDS.
#define PQ 68
#define PK 68
#define PV 72
#define PP 68
#define FLASH_SMEM ((64*PQ + 64*PK + 64*PV + 64*PP + 3*64) * 4)

__global__ __launch_bounds__(256) void flash_tf32(
    const float* __restrict__ Qg, const float* __restrict__ Kg,
    const float* __restrict__ Vg, const unsigned* __restrict__ mp,
    float* __restrict__ Og)
{
    extern __shared__ float sm[];
    float* Qs = sm;                 // [64][PQ]
    float* Ks = Qs + 64 * PQ;       // [64][PK]
    float* Vs = Ks + 64 * PK;       // [64][PV]
    float* Ps = Vs + 64 * PV;       // [64][PP]
    float* row_m = Ps + 64 * PP;
    float* row_l = row_m + 64;
    float* row_s = row_l + 64;

    const int bh = blockIdx.x;
    const int b = bh >> 4, h = bh & 15;
    const int q0 = blockIdx.y * 64;
    const int tid = threadIdx.x, wid = tid >> 5, lane = tid & 31;
    const int g = lane >> 2, t = lane & 3;
    const int wm = (wid & 3) * 16, wn = (wid >> 2) * 32;

    const float slope = exp2f(-0.5f * (float)(h + 1));
    const float inv_scale = 1.0f / 32.0f;

    // Q tile load (tf32-rounded)
    const float* Qb = Qg + ((size_t)b * SEQ + q0) * DMODEL + h * DHEAD;
    #pragma unroll
    for (int f = tid; f < 64 * 16; f += 256) {
        int r = f >> 4, c4 = (f & 15) * 4;
        float4 v = *(const float4*)&Qb[(size_t)r * DMODEL + c4];
        float4 cv = { f2tff(v.x), f2tff(v.y), f2tff(v.z), f2tff(v.w) };
        *(float4*)&Qs[r * PQ + c4] = cv;
    }
    if (tid < 64) { row_m[tid] = -3.0e38f; row_l[tid] = 0.0f; }

    float o[4][4] = {};

    for (int kt = 0; kt < SEQ; kt += 64) {
        __syncthreads();   // guard smem reuse (and Q/rows init on first iter)

        const float* Kb = Kg + ((size_t)b * SEQ + kt) * DMODEL + h * DHEAD;
        const float* Vb = Vg + ((size_t)b * SEQ + kt) * DMODEL + h * DHEAD;
        #pragma unroll
        for (int f = tid; f < 64 * 16; f += 256) {
            int r = f >> 4, c4 = (f & 15) * 4;
            float4 kv = *(const float4*)&Kb[(size_t)r * DMODEL + c4];
            float4 vv = *(const float4*)&Vb[(size_t)r * DMODEL + c4];
            float4 kc = { f2tff(kv.x), f2tff(kv.y), f2tff(kv.z), f2tff(kv.w) };
            float4 vc = { f2tff(vv.x), f2tff(vv.y), f2tff(vv.z), f2tff(vv.w) };
            *(float4*)&Ks[r * PK + c4] = kc;
            *(float4*)&Vs[r * PV + c4] = vc;
        }
        __syncthreads();

        // ---- S = Q K^T (warp tile 16x32) ----
        float s[4][4] = {};
        #pragma unroll
        for (int kk = 0; kk < 8; kk++) {
            unsigned a[4], bb[4][2];
            int ro = (wm + g) * PQ + kk * 8 + t;
            a[0] = __float_as_uint(Qs[ro]);
            a[1] = __float_as_uint(Qs[ro + 8 * PQ]);
            a[2] = __float_as_uint(Qs[ro + 4]);
            a[3] = __float_as_uint(Qs[ro + 8 * PQ + 4]);
            #pragma unroll
            for (int nt = 0; nt < 4; nt++) {
                int rb = (wn + nt * 8 + g) * PK + kk * 8 + t;
                bb[nt][0] = __float_as_uint(Ks[rb]);
                bb[nt][1] = __float_as_uint(Ks[rb + 4]);
            }
            #pragma unroll
            for (int nt = 0; nt < 4; nt++) mma8(s[nt], a, bb[nt]);
        }
        // spill S to smem (fp32)
        #pragma unroll
        for (int nt = 0; nt < 4; nt++) {
            int r0 = wm + g, c = wn + nt * 8 + 2 * t;
            Ps[r0 * PP + c]           = s[nt][0];
            Ps[r0 * PP + c + 1]       = s[nt][1];
            Ps[(r0 + 8) * PP + c]     = s[nt][2];
            Ps[(r0 + 8) * PP + c + 1] = s[nt][3];
        }
        __syncthreads();

        // ---- online softmax (4 threads per row, 16 cols each) ----
        {
            int r = tid >> 2, part = tid & 3;
            int q = q0 + r;
            unsigned wbits = mp[((size_t)b * SEQ + q) * (SEQ / 32) + (kt >> 5) + (part >> 1)];
            float logit[16];
            float mloc = -3.0e38f;
            #pragma unroll
            for (int c = 0; c < 16; c++) {
                int kg = kt + part * 16 + c;
                float val = (Ps[r * PP + part * 16 + c]
                             - slope * fabsf((float)(q - kg))) * inv_scale;
                if (!((wbits >> ((part & 1) * 16 + c)) & 1u)) val = -1.0e9f;
                logit[c] = val;
                mloc = fmaxf(mloc, val);
            }
            mloc = fmaxf(mloc, __shfl_xor_sync(0xffffffffu, mloc, 1));
            mloc = fmaxf(mloc, __shfl_xor_sync(0xffffffffu, mloc, 2));
            float mold = row_m[r];
            float mnew = fmaxf(mold, mloc);
            float sum = 0.0f;
            #pragma unroll
            for (int c = 0; c < 16; c++) {
                float p = expf(logit[c] - mnew);
                Ps[r * PP + part * 16 + c] = f2tff(p);   // P stored tf32-rounded
                sum += p;
            }
            sum += __shfl_xor_sync(0xffffffffu, sum, 1);
            sum += __shfl_xor_sync(0xffffffffu, sum, 2);
            if (part == 0) {
                float resc = expf(mold - mnew);
                row_m[r] = mnew;
                row_l[r] = row_l[r] * resc + sum;
                row_s[r] = resc;
            }
        }
        __syncthreads();

        // ---- rescale O, then O += P V ----
        {
            float r0 = row_s[wm + g], r1 = row_s[wm + 8 + g];
            #pragma unroll
            for (int nt = 0; nt < 4; nt++) {
                o[nt][0] *= r0; o[nt][1] *= r0;
                o[nt][2] *= r1; o[nt][3] *= r1;
            }
        }
        #pragma unroll
        for (int kk = 0; kk < 8; kk++) {
            unsigned a[4], bb[4][2];
            int ro = (wm + g) * PP + kk * 8 + t;
            a[0] = __float_as_uint(Ps[ro]);
            a[1] = __float_as_uint(Ps[ro + 8 * PP]);
            a[2] = __float_as_uint(Ps[ro + 4]);
            a[3] = __float_as_uint(Ps[ro + 8 * PP + 4]);
            #pragma unroll
            for (int nt = 0; nt < 4; nt++) {
                int rb = (kk * 8 + t) * PV + wn + nt * 8 + g;
                bb[nt][0] = __float_as_uint(Vs[rb]);
                bb[nt][1] = __float_as_uint(Vs[rb + 4 * PV]);
            }
            #pragma unroll
            for (int nt = 0; nt < 4; nt++) mma8(o[nt], a, bb[nt]);
        }
    }

    // normalize + store
    {
        float invl0 = 1.0f / row_l[wm + g];
        float invl1 = 1.0f / row_l[wm + 8 + g];
        int row0 = q0 + wm + g;
        #pragma unroll
        for (int nt = 0; nt < 4; nt++) {
            int col = h * DHEAD + wn + nt * 8 + 2 * t;
            float2 v0 = { o[nt][0] * invl0, o[nt][1] * invl0 };
            float2 v1 = { o[nt][2] * invl1, o[nt][3] * invl1 };
            *(float2*)&Og[((size_t)b * SEQ + row0) * DMODEL + col] = v0;
            *(float2*)&Og[((size_t)b * SEQ + row0 + 8) * DMODEL + col] = v1;
        }
    }
}

// ---------------- launcher ----------------
extern "C" void kernel_launch(void* const* d_in, const int* in_sizes, int n_in,
                              void* d_out, int out_size)
{
    const float* embed = (const float*)d_in[0];
    const float* keyi  = (const float*)d_in[1];
    const int*   mask  = (const int*)  d_in[2];
    const float* Wq    = (const float*)d_in[3];
    const float* bq    = (const float*)d_in[4];
    const float* Wk    = (const float*)d_in[5];
    const float* bk    = (const float*)d_in[6];
    const float* Wv    = (const float*)d_in[7];
    const float* bv    = (const float*)d_in[8];
    const float* Wo    = (const float*)d_in[9];
    const float* bo    = (const float*)d_in[10];
    float* out = (float*)d_out;

    float *Qp, *Kp, *Vp, *Ap; unsigned* MPp;
    cudaGetSymbolAddress((void**)&Qp, g_Q);
    cudaGetSymbolAddress((void**)&Kp, g_K);
    cudaGetSymbolAddress((void**)&Vp, g_V);
    cudaGetSymbolAddress((void**)&Ap, g_AO);
    cudaGetSymbolAddress((void**)&MPp, g_MP);

    const int smem_plain = 2 * 128 * GPA * 4;   // 36864
    const int smem_split = 4 * 128 * GPA * 4;   // 73728
    cudaFuncSetAttribute(gemm_tf32<true>,
                         cudaFuncAttributeMaxDynamicSharedMemorySize, smem_split);
    cudaFuncSetAttribute(flash_tf32,
                         cudaFuncAttributeMaxDynamicSharedMemorySize, FLASH_SMEM);

    pack_mask_kernel<<<(BATCH * SEQ * SEQ) / 256, 256>>>(mask, MPp);

    dim3 gp(DMODEL / 128, MROWS / 128);   // (8, 32)
    gemm_tf32<false><<<gp, 256, smem_plain>>>(embed, Wq, bq, Qp);
    gemm_tf32<false><<<gp, 256, smem_plain>>>(keyi,  Wk, bk, Kp);
    gemm_tf32<true ><<<gp, 256, smem_split>>>(keyi,  Wv, bv, Vp);

    flash_tf32<<<dim3(BATCH * NHEADS, SEQ / 64), 256, FLASH_SMEM>>>(Qp, Kp, Vp, MPp, Ap);

    gemm_tf32<true ><<<gp, 256, smem_split>>>(Ap, Wo, bo, out);
}

// round 3
// speedup vs baseline: 3.2009x; 1.3526x over previous
#include <cuda_runtime.h>
#include <cuda_bf16.h>
#include <math.h>

#define BATCH 2
#define SEQ   2048
#define DMODEL 1024
#define NHEADS 16
#define DHEAD 64
#define MROWS (BATCH*SEQ)   // 4096

// ---------------- scratch (alloc-free rule: __device__ globals) ----------------
__device__ float g_Q[MROWS * DMODEL];
__device__ float g_K[MROWS * DMODEL];
__device__ float g_V[MROWS * DMODEL];
__device__ float g_AO[MROWS * DMODEL];
__device__ unsigned g_MP[(size_t)BATCH * SEQ * (SEQ / 32)];   // packed mask bits

// ---------------- tf32 / cp.async helpers ----------------
__device__ __forceinline__ unsigned f2tf(float x) {
    unsigned u; asm("cvt.rna.tf32.f32 %0, %1;" : "=r"(u) : "f"(x)); return u;
}
__device__ __forceinline__ float f2tff(float x) { return __uint_as_float(f2tf(x)); }

__device__ __forceinline__ void mma8(float d[4], const unsigned a[4], const unsigned b[2]) {
    asm volatile(
        "mma.sync.aligned.m16n8k8.row.col.f32.tf32.tf32.f32 "
        "{%0,%1,%2,%3},{%4,%5,%6,%7},{%8,%9},{%0,%1,%2,%3};"
        : "+f"(d[0]), "+f"(d[1]), "+f"(d[2]), "+f"(d[3])
        : "r"(a[0]), "r"(a[1]), "r"(a[2]), "r"(a[3]), "r"(b[0]), "r"(b[1]));
}

__device__ __forceinline__ void cpa16(float* smem_dst, const float* gsrc) {
    unsigned s = (unsigned)__cvta_generic_to_shared(smem_dst);
    asm volatile("cp.async.cg.shared.global [%0], [%1], 16;" :: "r"(s), "l"(gsrc));
}
__device__ __forceinline__ void cp_commit() {
    asm volatile("cp.async.commit_group;");
}
template<int N>
__device__ __forceinline__ void cp_wait() {
    asm volatile("cp.async.wait_group %0;" :: "n"(N));
}

// ---------------- mask bit-packing ----------------
__global__ void pack_mask_kernel(const int* __restrict__ m, unsigned* __restrict__ p) {
    size_t i = (size_t)blockIdx.x * blockDim.x + threadIdx.x;
    unsigned bal = __ballot_sync(0xffffffffu, m[i] != 0);
    if ((threadIdx.x & 31) == 0) p[i >> 5] = bal;
}

// ---------------- tf32 GEMM:  C = A * W^T + bias (cp.async 2-stage) ----------------
// A: [M,1024], W: [1024,1024] row-major (K contiguous), C: [M,1024]
// Block tile 128x128, BK=32, 8 warps, warp tile 64x32 (m16n8k8).
#define GPA 36   // smem pitch (floats) -> conflict-free fragment LDS
#define GSTG (2 * 128 * GPA)   // floats per stage (A tile + W tile)

__global__ __launch_bounds__(256, 2) void gemm_tf32(
    const float* __restrict__ A, const float* __restrict__ W,
    const float* __restrict__ bias, float* __restrict__ C)
{
    const int Kd = DMODEL, Nd = DMODEL;
    extern __shared__ float smg[];

    const int tid = threadIdx.x, wid = tid >> 5, lane = tid & 31;
    const int g = lane >> 2, t = lane & 3;
    const int wm = (wid & 1) * 64, wn = (wid >> 1) * 32;
    const int bm = blockIdx.y * 128, bn = blockIdx.x * 128;

    const int lr = tid >> 3, lc4 = (tid & 7) * 4;   // 128 rows x 8 float4-cols, 2 rows/iter... (tid covers 256 of 1024 slots)

    float acc[4][4][4];
    #pragma unroll
    for (int mt = 0; mt < 4; mt++)
        #pragma unroll
        for (int nt = 0; nt < 4; nt++)
            #pragma unroll
            for (int r = 0; r < 4; r++) acc[mt][nt][r] = 0.0f;

    // issue one k-chunk (32 cols) of A and W tiles into stage s
    auto issue = [&](int k0, int s) {
        float* Ad = smg + s * GSTG;
        float* Wd = Ad + 128 * GPA;
        #pragma unroll
        for (int i = 0; i < 4; i++) {
            int f = tid + i * 256;
            int r = f >> 3, c4 = (f & 7) * 4;
            cpa16(&Ad[r * GPA + c4], &A[(size_t)(bm + r) * Kd + k0 + c4]);
            cpa16(&Wd[r * GPA + c4], &W[(size_t)(bn + r) * Kd + k0 + c4]);
        }
        cp_commit();
    };

    issue(0, 0);

    const int NCH = Kd / 32;   // 32 chunks
    for (int kc = 0; kc < NCH; kc++) {
        int s = kc & 1;
        if (kc + 1 < NCH) { issue((kc + 1) * 32, (kc + 1) & 1); cp_wait<1>(); }
        else             { cp_wait<0>(); }
        __syncthreads();

        const float* Ah = smg + s * GSTG;
        const float* Wh = Ah + 128 * GPA;
        #pragma unroll
        for (int kk = 0; kk < 4; kk++) {
            unsigned a[4][4], b[4][2];
            #pragma unroll
            for (int mt = 0; mt < 4; mt++) {
                int ro = (wm + mt * 16 + g) * GPA + kk * 8 + t;
                a[mt][0] = f2tf(Ah[ro]);
                a[mt][1] = f2tf(Ah[ro + 8 * GPA]);
                a[mt][2] = f2tf(Ah[ro + 4]);
                a[mt][3] = f2tf(Ah[ro + 8 * GPA + 4]);
            }
            #pragma unroll
            for (int nt = 0; nt < 4; nt++) {
                int ro = (wn + nt * 8 + g) * GPA + kk * 8 + t;
                b[nt][0] = f2tf(Wh[ro]);
                b[nt][1] = f2tf(Wh[ro + 4]);
            }
            #pragma unroll
            for (int mt = 0; mt < 4; mt++)
                #pragma unroll
                for (int nt = 0; nt < 4; nt++)
                    mma8(acc[mt][nt], a[mt], b[nt]);
        }
        __syncthreads();
    }

    #pragma unroll
    for (int mt = 0; mt < 4; mt++)
        #pragma unroll
        for (int nt = 0; nt < 4; nt++) {
            int row = bm + wm + mt * 16 + g;
            int col = bn + wn + nt * 8 + 2 * t;
            float b0 = bias[col], b1 = bias[col + 1];
            float2 v0 = { acc[mt][nt][0] + b0, acc[mt][nt][1] + b1 };
            float2 v1 = { acc[mt][nt][2] + b0, acc[mt][nt][3] + b1 };
            *(float2*)&C[(size_t)row * Nd + col] = v0;
            *(float2*)&C[(size_t)(row + 8) * Nd + col] = v1;
        }
}

// ---------------- tf32 flash attention (cp.async 2-stage K/V) ----------------
#define PP 68   // pitch for Q-prologue buffer and P spill (same buffer)
#define PK 68
#define PV 72
// smem floats: K 2x64xPK + V 2x64xPV + QP 64xPP + 3x64
#define FLASH_SMEM ((2*64*PK + 2*64*PV + 64*PP + 3*64) * 4)

__global__ __launch_bounds__(256, 2) void flash_tf32(
    const float* __restrict__ Qg, const float* __restrict__ Kg,
    const float* __restrict__ Vg, const unsigned* __restrict__ mp,
    float* __restrict__ Og)
{
    extern __shared__ float sm[];
    float* Ks0 = sm;                    // [2][64][PK]
    float* Vs0 = Ks0 + 2 * 64 * PK;     // [2][64][PV]
    float* Ps  = Vs0 + 2 * 64 * PV;     // [64][PP]  (Q prologue, then P spill)
    float* row_m = Ps + 64 * PP;
    float* row_l = row_m + 64;
    float* row_s = row_l + 64;

    const int bh = blockIdx.x;
    const int b = bh >> 4, h = bh & 15;
    const int q0 = blockIdx.y * 64;
    const int tid = threadIdx.x, wid = tid >> 5, lane = tid & 31;
    const int g = lane >> 2, t = lane & 3;
    const int wm = (wid & 3) * 16, wn = (wid >> 2) * 32;

    const float slope = exp2f(-0.5f * (float)(h + 1));
    const float inv_scale = 1.0f / 32.0f;

    // ---- prologue: Q tile -> smem (tf32), issue K/V tile 0 ----
    const float* Qb = Qg + ((size_t)b * SEQ + q0) * DMODEL + h * DHEAD;
    #pragma unroll
    for (int f = tid; f < 64 * 16; f += 256) {
        int r = f >> 4, c4 = (f & 15) * 4;
        float4 v = *(const float4*)&Qb[(size_t)r * DMODEL + c4];
        float4 cv = { f2tff(v.x), f2tff(v.y), f2tff(v.z), f2tff(v.w) };
        *(float4*)&Ps[r * PP + c4] = cv;
    }
    if (tid < 64) { row_m[tid] = -3.0e38f; row_l[tid] = 0.0f; }

    auto issue_kv = [&](int kt, int s) {
        const float* Kb = Kg + ((size_t)b * SEQ + kt) * DMODEL + h * DHEAD;
        const float* Vb = Vg + ((size_t)b * SEQ + kt) * DMODEL + h * DHEAD;
        float* Kd = Ks0 + s * 64 * PK;
        float* Vd = Vs0 + s * 64 * PV;
        #pragma unroll
        for (int f = tid; f < 64 * 16; f += 256) {
            int r = f >> 4, c4 = (f & 15) * 4;
            cpa16(&Kd[r * PK + c4], &Kb[(size_t)r * DMODEL + c4]);
            cpa16(&Vd[r * PV + c4], &Vb[(size_t)r * DMODEL + c4]);
        }
        cp_commit();
    };

    issue_kv(0, 0);
    __syncthreads();   // Q tile visible to all

    // ---- hoist Q fragments into registers for the whole KV loop ----
    unsigned qf[8][4];
    #pragma unroll
    for (int kk = 0; kk < 8; kk++) {
        int ro = (wm + g) * PP + kk * 8 + t;
        qf[kk][0] = __float_as_uint(Ps[ro]);
        qf[kk][1] = __float_as_uint(Ps[ro + 8 * PP]);
        qf[kk][2] = __float_as_uint(Ps[ro + 4]);
        qf[kk][3] = __float_as_uint(Ps[ro + 8 * PP + 4]);
    }

    float o[4][4] = {};
    const int NIT = SEQ / 64;   // 32

    for (int it = 0; it < NIT; it++) {
        int s = it & 1;
        if (it + 1 < NIT) { issue_kv((it + 1) * 64, (it + 1) & 1); cp_wait<1>(); }
        else              { cp_wait<0>(); }
        __syncthreads();   // K/V[s] ready; also orders qf-LDS before Ps spill (it==0)

        const float* Ksm = Ks0 + s * 64 * PK;
        const float* Vsm = Vs0 + s * 64 * PV;
        int kt = it * 64;

        // ---- S = Q K^T (warp tile 16x32) ----
        float sacc[4][4] = {};
        #pragma unroll
        for (int kk = 0; kk < 8; kk++) {
            unsigned bb[4][2];
            #pragma unroll
            for (int nt = 0; nt < 4; nt++) {
                int rb = (wn + nt * 8 + g) * PK + kk * 8 + t;
                bb[nt][0] = f2tf(Ksm[rb]);
                bb[nt][1] = f2tf(Ksm[rb + 4]);
            }
            #pragma unroll
            for (int nt = 0; nt < 4; nt++) mma8(sacc[nt], qf[kk], bb[nt]);
        }
        // spill S to smem (fp32)
        #pragma unroll
        for (int nt = 0; nt < 4; nt++) {
            int r0 = wm + g, c = wn + nt * 8 + 2 * t;
            Ps[r0 * PP + c]           = sacc[nt][0];
            Ps[r0 * PP + c + 1]       = sacc[nt][1];
            Ps[(r0 + 8) * PP + c]     = sacc[nt][2];
            Ps[(r0 + 8) * PP + c + 1] = sacc[nt][3];
        }
        __syncthreads();

        // ---- online softmax (4 threads per row, 16 cols each) ----
        {
            int r = tid >> 2, part = tid & 3;
            int q = q0 + r;
            unsigned wbits = mp[((size_t)b * SEQ + q) * (SEQ / 32) + (kt >> 5) + (part >> 1)];
            float logit[16];
            float mloc = -3.0e38f;
            #pragma unroll
            for (int c = 0; c < 16; c++) {
                int kg = kt + part * 16 + c;
                float val = (Ps[r * PP + part * 16 + c]
                             - slope * fabsf((float)(q - kg))) * inv_scale;
                if (!((wbits >> ((part & 1) * 16 + c)) & 1u)) val = -1.0e9f;
                logit[c] = val;
                mloc = fmaxf(mloc, val);
            }
            mloc = fmaxf(mloc, __shfl_xor_sync(0xffffffffu, mloc, 1));
            mloc = fmaxf(mloc, __shfl_xor_sync(0xffffffffu, mloc, 2));
            float mold = row_m[r];
            float mnew = fmaxf(mold, mloc);
            float sum = 0.0f;
            #pragma unroll
            for (int c = 0; c < 16; c++) {
                float p = expf(logit[c] - mnew);
                Ps[r * PP + part * 16 + c] = f2tff(p);   // P stored tf32
                sum += p;
            }
            sum += __shfl_xor_sync(0xffffffffu, sum, 1);
            sum += __shfl_xor_sync(0xffffffffu, sum, 2);
            if (part == 0) {
                float resc = expf(mold - mnew);
                row_m[r] = mnew;
                row_l[r] = row_l[r] * resc + sum;
                row_s[r] = resc;
            }
        }
        __syncthreads();

        // ---- rescale O, then O += P V ----
        {
            float r0 = row_s[wm + g], r1 = row_s[wm + 8 + g];
            #pragma unroll
            for (int nt = 0; nt < 4; nt++) {
                o[nt][0] *= r0; o[nt][1] *= r0;
                o[nt][2] *= r1; o[nt][3] *= r1;
            }
        }
        #pragma unroll
        for (int kk = 0; kk < 8; kk++) {
            unsigned a[4], bb[4][2];
            int ro = (wm + g) * PP + kk * 8 + t;
            a[0] = __float_as_uint(Ps[ro]);
            a[1] = __float_as_uint(Ps[ro + 8 * PP]);
            a[2] = __float_as_uint(Ps[ro + 4]);
            a[3] = __float_as_uint(Ps[ro + 8 * PP + 4]);
            #pragma unroll
            for (int nt = 0; nt < 4; nt++) {
                int rb = (kk * 8 + t) * PV + wn + nt * 8 + g;
                bb[nt][0] = f2tf(Vsm[rb]);
                bb[nt][1] = f2tf(Vsm[rb + 4 * PV]);
            }
            #pragma unroll
            for (int nt = 0; nt < 4; nt++) mma8(o[nt], a, bb[nt]);
        }
        __syncthreads();   // all warps done with K/V[s] and Ps before next issue/spill
    }

    // ---- normalize + store ----
    {
        float invl0 = 1.0f / row_l[wm + g];
        float invl1 = 1.0f / row_l[wm + 8 + g];
        int row0 = q0 + wm + g;
        #pragma unroll
        for (int nt = 0; nt < 4; nt++) {
            int col = h * DHEAD + wn + nt * 8 + 2 * t;
            float2 v0 = { o[nt][0] * invl0, o[nt][1] * invl0 };
            float2 v1 = { o[nt][2] * invl1, o[nt][3] * invl1 };
            *(float2*)&Og[((size_t)b * SEQ + row0) * DMODEL + col] = v0;
            *(float2*)&Og[((size_t)b * SEQ + row0 + 8) * DMODEL + col] = v1;
        }
    }
}

// ---------------- launcher ----------------
extern "C" void kernel_launch(void* const* d_in, const int* in_sizes, int n_in,
                              void* d_out, int out_size)
{
    const float* embed = (const float*)d_in[0];
    const float* keyi  = (const float*)d_in[1];
    const int*   mask  = (const int*)  d_in[2];
    const float* Wq    = (const float*)d_in[3];
    const float* bq    = (const float*)d_in[4];
    const float* Wk    = (const float*)d_in[5];
    const float* bk    = (const float*)d_in[6];
    const float* Wv    = (const float*)d_in[7];
    const float* bv    = (const float*)d_in[8];
    const float* Wo    = (const float*)d_in[9];
    const float* bo    = (const float*)d_in[10];
    float* out = (float*)d_out;

    float *Qp, *Kp, *Vp, *Ap; unsigned* MPp;
    cudaGetSymbolAddress((void**)&Qp, g_Q);
    cudaGetSymbolAddress((void**)&Kp, g_K);
    cudaGetSymbolAddress((void**)&Vp, g_V);
    cudaGetSymbolAddress((void**)&Ap, g_AO);
    cudaGetSymbolAddress((void**)&MPp, g_MP);

    const int smem_gemm = 2 * GSTG * 4;   // 73728
    cudaFuncSetAttribute(gemm_tf32,
                         cudaFuncAttributeMaxDynamicSharedMemorySize, smem_gemm);
    cudaFuncSetAttribute(flash_tf32,
                         cudaFuncAttributeMaxDynamicSharedMemorySize, FLASH_SMEM);

    pack_mask_kernel<<<(BATCH * SEQ * SEQ) / 256, 256>>>(mask, MPp);

    dim3 gp(DMODEL / 128, MROWS / 128);   // (8, 32)
    gemm_tf32<<<gp, 256, smem_gemm>>>(embed, Wq, bq, Qp);
    gemm_tf32<<<gp, 256, smem_gemm>>>(keyi,  Wk, bk, Kp);
    gemm_tf32<<<gp, 256, smem_gemm>>>(keyi,  Wv, bv, Vp);

    flash_tf32<<<dim3(BATCH * NHEADS, SEQ / 64), 256, FLASH_SMEM>>>(Qp, Kp, Vp, MPp, Ap);

    gemm_tf32<<<gp, 256, smem_gemm>>>(Ap, Wo, bo, out);
}

// round 4
// speedup vs baseline: 3.7047x; 1.1574x over previous
#include <cuda_runtime.h>
#include <cuda_bf16.h>
#include <math.h>

#define BATCH 2
#define SEQ   2048
#define DMODEL 1024
#define NHEADS 16
#define DHEAD 64
#define MROWS (BATCH*SEQ)   // 4096

// ---------------- scratch (alloc-free rule: __device__ globals) ----------------
__device__ float g_Q[MROWS * DMODEL];
__device__ float g_K[MROWS * DMODEL];
__device__ float g_V[MROWS * DMODEL];
__device__ float g_AO[MROWS * DMODEL];
__device__ unsigned g_MP[(size_t)BATCH * SEQ * (SEQ / 32)];   // packed mask bits

// ---------------- helpers ----------------
__device__ __forceinline__ unsigned f2tf(float x) {
    unsigned u; asm("cvt.rna.tf32.f32 %0, %1;" : "=r"(u) : "f"(x)); return u;
}
__device__ __forceinline__ float f2tff(float x) { return __uint_as_float(f2tf(x)); }
__device__ __forceinline__ float ex2(float x) {
    float y; asm("ex2.approx.f32 %0, %1;" : "=f"(y) : "f"(x)); return y;
}

__device__ __forceinline__ void mma8(float d[4], const unsigned a[4], const unsigned b[2]) {
    asm volatile(
        "mma.sync.aligned.m16n8k8.row.col.f32.tf32.tf32.f32 "
        "{%0,%1,%2,%3},{%4,%5,%6,%7},{%8,%9},{%0,%1,%2,%3};"
        : "+f"(d[0]), "+f"(d[1]), "+f"(d[2]), "+f"(d[3])
        : "r"(a[0]), "r"(a[1]), "r"(a[2]), "r"(a[3]), "r"(b[0]), "r"(b[1]));
}

__device__ __forceinline__ void cpa16(float* smem_dst, const float* gsrc) {
    unsigned s = (unsigned)__cvta_generic_to_shared(smem_dst);
    asm volatile("cp.async.cg.shared.global [%0], [%1], 16;" :: "r"(s), "l"(gsrc));
}
__device__ __forceinline__ void cp_commit() { asm volatile("cp.async.commit_group;"); }
template<int N>
__device__ __forceinline__ void cp_wait() {
    asm volatile("cp.async.wait_group %0;" :: "n"(N));
}

// ---------------- mask bit-packing ----------------
__global__ void pack_mask_kernel(const int* __restrict__ m, unsigned* __restrict__ p) {
    size_t i = (size_t)blockIdx.x * blockDim.x + threadIdx.x;
    unsigned bal = __ballot_sync(0xffffffffu, m[i] != 0);
    if ((threadIdx.x & 31) == 0) p[i >> 5] = bal;
}

// ---------------- tf32 GEMM core:  C = A * W^T + bias (cp.async 2-stage) ----------------
#define GPA 36
#define GSTG (2 * 128 * GPA)

template<bool RND, bool CVTA>
__device__ __forceinline__ void gemm_core(
    const float* __restrict__ A, const float* __restrict__ W,
    const float* __restrict__ bias, float* __restrict__ C,
    float* smg, int bm, int bn)
{
    const int Kd = DMODEL, Nd = DMODEL;
    const int tid = threadIdx.x, wid = tid >> 5, lane = tid & 31;
    const int g = lane >> 2, t = lane & 3;
    const int wm = (wid & 1) * 64, wn = (wid >> 1) * 32;

    float acc[4][4][4];
    #pragma unroll
    for (int mt = 0; mt < 4; mt++)
        #pragma unroll
        for (int nt = 0; nt < 4; nt++)
            #pragma unroll
            for (int r = 0; r < 4; r++) acc[mt][nt][r] = 0.0f;

    auto issue = [&](int k0, int s) {
        float* Ad = smg + s * GSTG;
        float* Wd = Ad + 128 * GPA;
        #pragma unroll
        for (int i = 0; i < 4; i++) {
            int f = tid + i * 256;
            int r = f >> 3, c4 = (f & 7) * 4;
            cpa16(&Ad[r * GPA + c4], &A[(size_t)(bm + r) * Kd + k0 + c4]);
            cpa16(&Wd[r * GPA + c4], &W[(size_t)(bn + r) * Kd + k0 + c4]);
        }
        cp_commit();
    };

    issue(0, 0);

    const int NCH = Kd / 32;
    for (int kc = 0; kc < NCH; kc++) {
        int s = kc & 1;
        if (kc + 1 < NCH) { issue((kc + 1) * 32, (kc + 1) & 1); cp_wait<1>(); }
        else             { cp_wait<0>(); }
        __syncthreads();

        const float* Ah = smg + s * GSTG;
        const float* Wh = Ah + 128 * GPA;
        #pragma unroll
        for (int kk = 0; kk < 4; kk++) {
            unsigned a[4][4], b[4][2];
            #pragma unroll
            for (int mt = 0; mt < 4; mt++) {
                int ro = (wm + mt * 16 + g) * GPA + kk * 8 + t;
                if (CVTA) {
                    a[mt][0] = f2tf(Ah[ro]);
                    a[mt][1] = f2tf(Ah[ro + 8 * GPA]);
                    a[mt][2] = f2tf(Ah[ro + 4]);
                    a[mt][3] = f2tf(Ah[ro + 8 * GPA + 4]);
                } else {
                    a[mt][0] = __float_as_uint(Ah[ro]);
                    a[mt][1] = __float_as_uint(Ah[ro + 8 * GPA]);
                    a[mt][2] = __float_as_uint(Ah[ro + 4]);
                    a[mt][3] = __float_as_uint(Ah[ro + 8 * GPA + 4]);
                }
            }
            #pragma unroll
            for (int nt = 0; nt < 4; nt++) {
                int ro = (wn + nt * 8 + g) * GPA + kk * 8 + t;
                b[nt][0] = f2tf(Wh[ro]);
                b[nt][1] = f2tf(Wh[ro + 4]);
            }
            #pragma unroll
            for (int mt = 0; mt < 4; mt++)
                #pragma unroll
                for (int nt = 0; nt < 4; nt++)
                    mma8(acc[mt][nt], a[mt], b[nt]);
        }
        __syncthreads();
    }

    #pragma unroll
    for (int mt = 0; mt < 4; mt++)
        #pragma unroll
        for (int nt = 0; nt < 4; nt++) {
            int row = bm + wm + mt * 16 + g;
            int col = bn + wn + nt * 8 + 2 * t;
            float b0 = bias[col], b1 = bias[col + 1];
            float r00 = acc[mt][nt][0] + b0, r01 = acc[mt][nt][1] + b1;
            float r10 = acc[mt][nt][2] + b0, r11 = acc[mt][nt][3] + b1;
            if (RND) { r00 = f2tff(r00); r01 = f2tff(r01); r10 = f2tff(r10); r11 = f2tff(r11); }
            float2 v0 = { r00, r01 }, v1 = { r10, r11 };
            *(float2*)&C[(size_t)row * Nd + col] = v0;
            *(float2*)&C[(size_t)(row + 8) * Nd + col] = v1;
        }
}

// merged Q/K/V projections: blockIdx.z selects which
__global__ __launch_bounds__(256, 2) void qkv_gemm(
    const float* __restrict__ embed, const float* __restrict__ keyi,
    const float* __restrict__ Wq, const float* __restrict__ bq,
    const float* __restrict__ Wk, const float* __restrict__ bk,
    const float* __restrict__ Wv, const float* __restrict__ bv,
    float* __restrict__ Qo, float* __restrict__ Ko, float* __restrict__ Vo)
{
    extern __shared__ float smg[];
    const int bm = blockIdx.y * 128, bn = blockIdx.x * 128;
    const int z = blockIdx.z;
    const float* A = (z == 0) ? embed : keyi;
    const float* W = (z == 0) ? Wq : (z == 1) ? Wk : Wv;
    const float* bias = (z == 0) ? bq : (z == 1) ? bk : bv;
    float* C = (z == 0) ? Qo : (z == 1) ? Ko : Vo;
    gemm_core<true, true>(A, W, bias, C, smg, bm, bn);
}

__global__ __launch_bounds__(256, 2) void oproj_gemm(
    const float* __restrict__ A, const float* __restrict__ W,
    const float* __restrict__ bias, float* __restrict__ C)
{
    extern __shared__ float smg[];
    gemm_core<false, false>(A, W, bias, C, smg, blockIdx.y * 128, blockIdx.x * 128);
}

// ---------------- flash attention: TQ=128, warp-owned rows ----------------
#define PK 68
#define PV 72
#define PP 68
#define FLASH_SMEM ((2*64*PK + 2*64*PV + 128*PP) * 4)

__global__ __launch_bounds__(256, 2) void flash_tf32(
    const float* __restrict__ Qg, const float* __restrict__ Kg,
    const float* __restrict__ Vg, const unsigned* __restrict__ mp,
    float* __restrict__ Og)
{
    extern __shared__ float sm[];
    float* Ks0 = sm;                    // [2][64][PK]
    float* Vs0 = Ks0 + 2 * 64 * PK;     // [2][64][PV]
    float* Ps  = Vs0 + 2 * 64 * PV;     // [128][PP]  (Q stage, then per-warp P strips)

    const int bh = blockIdx.x;
    const int b = bh >> 4, h = bh & 15;
    const int q0 = blockIdx.y * 128;
    const int tid = threadIdx.x, wid = tid >> 5, lane = tid & 31;
    const int g = lane >> 2, t = lane & 3;

    const float LOG2E = 1.4426950408889634f;
    const float c1 = LOG2E / 32.0f;                       // inv_scale in base-2
    const float slope2 = exp2f(-0.5f * (float)(h + 1)) * c1;
    const float MSK2 = -1.0e9f * LOG2E;                   // masked logit (base-2)

    auto issue_kv = [&](int kt, int s) {
        const float* Kb = Kg + ((size_t)b * SEQ + kt) * DMODEL + h * DHEAD;
        const float* Vb = Vg + ((size_t)b * SEQ + kt) * DMODEL + h * DHEAD;
        float* Kd = Ks0 + s * 64 * PK;
        float* Vd = Vs0 + s * 64 * PV;
        #pragma unroll
        for (int f = tid; f < 64 * 16; f += 256) {
            int r = f >> 4, c4 = (f & 15) * 4;
            cpa16(&Kd[r * PK + c4], &Kb[(size_t)r * DMODEL + c4]);
            cpa16(&Vd[r * PV + c4], &Vb[(size_t)r * DMODEL + c4]);
        }
        cp_commit();
    };

    issue_kv(0, 0);

    // stage Q (already tf32-rounded by projection epilogue)
    const float* Qb = Qg + ((size_t)b * SEQ + q0) * DMODEL + h * DHEAD;
    #pragma unroll
    for (int f = tid; f < 128 * 16; f += 256) {
        int r = f >> 4, c4 = (f & 15) * 4;
        *(float4*)&Ps[r * PP + c4] = *(const float4*)&Qb[(size_t)r * DMODEL + c4];
    }
    __syncthreads();

    const int prow = (wid * 16 + g) * PP;
    unsigned qf[8][4];
    #pragma unroll
    for (int kk = 0; kk < 8; kk++) {
        qf[kk][0] = __float_as_uint(Ps[prow + kk * 8 + t]);
        qf[kk][1] = __float_as_uint(Ps[prow + 8 * PP + kk * 8 + t]);
        qf[kk][2] = __float_as_uint(Ps[prow + kk * 8 + t + 4]);
        qf[kk][3] = __float_as_uint(Ps[prow + 8 * PP + kk * 8 + t + 4]);
    }
    __syncwarp();

    float o[8][4];
    #pragma unroll
    for (int nt = 0; nt < 8; nt++)
        #pragma unroll
        for (int r = 0; r < 4; r++) o[nt][r] = 0.0f;
    float m0 = -3.0e38f, m1 = -3.0e38f, l0 = 0.0f, l1 = 0.0f;

    const int r0g = q0 + wid * 16 + g;         // global q row (row1 = r0g+8)
    const unsigned* mbase = mp + ((size_t)b * SEQ + r0g) * (SEQ / 32);

    const int NIT = SEQ / 64;   // 32
    for (int it = 0; it < NIT; it++) {
        int s = it & 1;
        cp_wait<0>();
        __syncthreads();                        // KV[s] ready; buffer s^1 free
        if (it + 1 < NIT) issue_kv((it + 1) * 64, s ^ 1);

        const float* Ksm = Ks0 + s * 64 * PK;
        const float* Vsm = Vs0 + s * 64 * PV;
        const int kt = it * 64;

        // ---- S = Q K^T (warp tile 16x64) ----
        float sa[8][4];
        #pragma unroll
        for (int nt = 0; nt < 8; nt++)
            #pragma unroll
            for (int r = 0; r < 4; r++) sa[nt][r] = 0.0f;
        #pragma unroll
        for (int kk = 0; kk < 8; kk++) {
            unsigned bb[8][2];
            #pragma unroll
            for (int nt = 0; nt < 8; nt++) {
                int rb = (nt * 8 + g) * PK + kk * 8 + t;
                bb[nt][0] = __float_as_uint(Ksm[rb]);
                bb[nt][1] = __float_as_uint(Ksm[rb + 4]);
            }
            #pragma unroll
            for (int nt = 0; nt < 8; nt++) mma8(sa[nt], qf[kk], bb[nt]);
        }

        // ---- logits (alibi + scale + mask), warp-local online softmax ----
        uint2 mw0 = *(const uint2*)(mbase + (kt >> 5));
        uint2 mw1 = *(const uint2*)(mbase + 8 * (SEQ / 32) + (kt >> 5));
        float mx0 = -3.0e38f, mx1 = -3.0e38f;
        #pragma unroll
        for (int nt = 0; nt < 8; nt++) {
            int col = nt * 8 + 2 * t;
            float k0f = (float)(kt + col), k1f = k0f + 1.0f;
            float e00 = sa[nt][0] * c1 - slope2 * fabsf((float)r0g - k0f);
            float e01 = sa[nt][1] * c1 - slope2 * fabsf((float)r0g - k1f);
            float e10 = sa[nt][2] * c1 - slope2 * fabsf((float)(r0g + 8) - k0f);
            float e11 = sa[nt][3] * c1 - slope2 * fabsf((float)(r0g + 8) - k1f);
            unsigned s0b = (col < 32) ? (mw0.x >> col) : (mw0.y >> (col - 32));
            unsigned s1b = (col < 32) ? (mw1.x >> col) : (mw1.y >> (col - 32));
            if (!(s0b & 1u)) e00 = MSK2;
            if (!(s0b & 2u)) e01 = MSK2;
            if (!(s1b & 1u)) e10 = MSK2;
            if (!(s1b & 2u)) e11 = MSK2;
            sa[nt][0] = e00; sa[nt][1] = e01; sa[nt][2] = e10; sa[nt][3] = e11;
            mx0 = fmaxf(mx0, fmaxf(e00, e01));
            mx1 = fmaxf(mx1, fmaxf(e10, e11));
        }
        mx0 = fmaxf(mx0, __shfl_xor_sync(0xffffffffu, mx0, 1));
        mx0 = fmaxf(mx0, __shfl_xor_sync(0xffffffffu, mx0, 2));
        mx1 = fmaxf(mx1, __shfl_xor_sync(0xffffffffu, mx1, 1));
        mx1 = fmaxf(mx1, __shfl_xor_sync(0xffffffffu, mx1, 2));
        float m0n = fmaxf(m0, mx0), m1n = fmaxf(m1, mx1);

        float s0 = 0.0f, s1 = 0.0f;
        #pragma unroll
        for (int nt = 0; nt < 8; nt++) {
            float p00 = ex2(sa[nt][0] - m0n), p01 = ex2(sa[nt][1] - m0n);
            float p10 = ex2(sa[nt][2] - m1n), p11 = ex2(sa[nt][3] - m1n);
            s0 += p00 + p01; s1 += p10 + p11;
            float2 v0 = { f2tff(p00), f2tff(p01) };
            float2 v1 = { f2tff(p10), f2tff(p11) };
            *(float2*)&Ps[prow + nt * 8 + 2 * t] = v0;
            *(float2*)&Ps[prow + 8 * PP + nt * 8 + 2 * t] = v1;
        }
        s0 += __shfl_xor_sync(0xffffffffu, s0, 1);
        s0 += __shfl_xor_sync(0xffffffffu, s0, 2);
        s1 += __shfl_xor_sync(0xffffffffu, s1, 1);
        s1 += __shfl_xor_sync(0xffffffffu, s1, 2);

        float sc0 = ex2(m0 - m0n), sc1 = ex2(m1 - m1n);
        l0 = l0 * sc0 + s0; l1 = l1 * sc1 + s1;
        m0 = m0n; m1 = m1n;
        #pragma unroll
        for (int nt = 0; nt < 8; nt++) {
            o[nt][0] *= sc0; o[nt][1] *= sc0;
            o[nt][2] *= sc1; o[nt][3] *= sc1;
        }
        __syncwarp();   // P strip visible within warp

        // ---- O += P V (warp-local) ----
        #pragma unroll
        for (int kk = 0; kk < 8; kk++) {
            unsigned a[4];
            a[0] = __float_as_uint(Ps[prow + kk * 8 + t]);
            a[1] = __float_as_uint(Ps[prow + 8 * PP + kk * 8 + t]);
            a[2] = __float_as_uint(Ps[prow + kk * 8 + t + 4]);
            a[3] = __float_as_uint(Ps[prow + 8 * PP + kk * 8 + t + 4]);
            unsigned bb[8][2];
            #pragma unroll
            for (int nt = 0; nt < 8; nt++) {
                int rb = (kk * 8 + t) * PV + nt * 8 + g;
                bb[nt][0] = __float_as_uint(Vsm[rb]);
                bb[nt][1] = __float_as_uint(Vsm[rb + 4 * PV]);
            }
            #pragma unroll
            for (int nt = 0; nt < 8; nt++) mma8(o[nt], a, bb[nt]);
        }
        // loop-top __syncthreads orders next-iteration reuse
    }

    // ---- normalize + store (rounded for O-proj's CVTA=false) ----
    {
        float inv0 = 1.0f / l0, inv1 = 1.0f / l1;
        #pragma unroll
        for (int nt = 0; nt < 8; nt++) {
            int col = h * DHEAD + nt * 8 + 2 * t;
            float2 v0 = { f2tff(o[nt][0] * inv0), f2tff(o[nt][1] * inv0) };
            float2 v1 = { f2tff(o[nt][2] * inv1), f2tff(o[nt][3] * inv1) };
            *(float2*)&Og[((size_t)b * SEQ + r0g) * DMODEL + col] = v0;
            *(float2*)&Og[((size_t)b * SEQ + r0g + 8) * DMODEL + col] = v1;
        }
    }
}

// ---------------- launcher ----------------
extern "C" void kernel_launch(void* const* d_in, const int* in_sizes, int n_in,
                              void* d_out, int out_size)
{
    const float* embed = (const float*)d_in[0];
    const float* keyi  = (const float*)d_in[1];
    const int*   mask  = (const int*)  d_in[2];
    const float* Wq    = (const float*)d_in[3];
    const float* bq    = (const float*)d_in[4];
    const float* Wk    = (const float*)d_in[5];
    const float* bk    = (const float*)d_in[6];
    const float* Wv    = (const float*)d_in[7];
    const float* bv    = (const float*)d_in[8];
    const float* Wo    = (const float*)d_in[9];
    const float* bo    = (const float*)d_in[10];
    float* out = (float*)d_out;

    float *Qp, *Kp, *Vp, *Ap; unsigned* MPp;
    cudaGetSymbolAddress((void**)&Qp, g_Q);
    cudaGetSymbolAddress((void**)&Kp, g_K);
    cudaGetSymbolAddress((void**)&Vp, g_V);
    cudaGetSymbolAddress((void**)&Ap, g_AO);
    cudaGetSymbolAddress((void**)&MPp, g_MP);

    const int smem_gemm = 2 * GSTG * 4;   // 73728
    cudaFuncSetAttribute(qkv_gemm,
                         cudaFuncAttributeMaxDynamicSharedMemorySize, smem_gemm);
    cudaFuncSetAttribute(oproj_gemm,
                         cudaFuncAttributeMaxDynamicSharedMemorySize, smem_gemm);
    cudaFuncSetAttribute(flash_tf32,
                         cudaFuncAttributeMaxDynamicSharedMemorySize, FLASH_SMEM);

    pack_mask_kernel<<<(BATCH * SEQ * SEQ) / 256, 256>>>(mask, MPp);

    dim3 gqkv(DMODEL / 128, MROWS / 128, 3);   // (8, 32, 3) = 768 blocks
    qkv_gemm<<<gqkv, 256, smem_gemm>>>(embed, keyi, Wq, bq, Wk, bk, Wv, bv, Qp, Kp, Vp);

    flash_tf32<<<dim3(BATCH * NHEADS, SEQ / 128), 256, FLASH_SMEM>>>(Qp, Kp, Vp, MPp, Ap);

    dim3 gp(DMODEL / 128, MROWS / 128);        // (8, 32)
    oproj_gemm<<<gp, 256, smem_gemm>>>(Ap, Wo, bo, out);
}